// round 3
// baseline (speedup 1.0000x reference)
#include <cuda_runtime.h>

#define UU      64
#define IIN     6
#define TLEN    8192
#define BSZ     256
#define MSZ     16
#define UNFOLDS 6
#define EPSV    1e-8f

// Precomputed parameter tables (filled by prep_kernel each launch; deterministic).
// g_P[i*UU+j] = (A, B, wn, wd):
//   tanh arg  z = fma(v_i, A, B)  with A = 0.5*sigma, B = -0.5*sigma*mu
//   num += wn * tanh(z)  (wn = 0.5*w*erev),  den += wd * tanh(z) (wd = 0.5*w)
__device__ float4 g_P[UU * UU];
// Sensory, affine-in-x folded through input_w/input_b:
// g_SP[i*UU+j] = (SA, SB, swn, swd), z = fma(x_i, SA, SB)
__device__ float4 g_SP[IIN * UU];
// Per-j folded constants:
//   g_Cn[j] = gleak*vleak + sum_i wn_ij + sum_i swn_ij
//   g_Cd[j] = cm_t + gleak + sum_i wd_ij + sum_i swd_ij + EPS
__device__ float g_Cn[UU];
__device__ float g_Cd[UU];
__device__ float g_cmt[UU];

__global__ void prep_kernel(
    const float* __restrict__ gleak, const float* __restrict__ vleak,
    const float* __restrict__ cm,
    const float* __restrict__ sigma, const float* __restrict__ mu,
    const float* __restrict__ w,     const float* __restrict__ erev,
    const float* __restrict__ ssig,  const float* __restrict__ smu,
    const float* __restrict__ sw,    const float* __restrict__ serev,
    const float* __restrict__ iw,    const float* __restrict__ ib)
{
    int id = blockIdx.x * blockDim.x + threadIdx.x;
    if (id < UU * UU) {
        float s = sigma[id], m = mu[id], ww = w[id], e = erev[id];
        g_P[id] = make_float4(0.5f * s, -0.5f * s * m, 0.5f * ww * e, 0.5f * ww);
    }
    if (id < IIN * UU) {
        int i = id / UU;
        float s = ssig[id], m = smu[id], ww = sw[id], e = serev[id];
        g_SP[id] = make_float4(0.5f * s * iw[i], 0.5f * s * (ib[i] - m),
                               0.5f * ww * e, 0.5f * ww);
    }
    if (id < UU) {
        int j = id;
        float sn = 0.f, sd = 0.f;
        for (int i = 0; i < UU; i++) {
            float ww = w[i * UU + j];
            sn += 0.5f * ww * erev[i * UU + j];
            sd += 0.5f * ww;
        }
        for (int i = 0; i < IIN; i++) {
            float ww = sw[i * UU + j];
            sn += 0.5f * ww * serev[i * UU + j];
            sd += 0.5f * ww;
        }
        float cmt = cm[j] * (float)UNFOLDS;  // cm / (ELAPSED/ODE_UNFOLDS), ELAPSED=1
        g_cmt[j] = cmt;
        g_Cn[j]  = gleak[j] * vleak[j] + sn;
        g_Cd[j]  = cmt + gleak[j] + sd + EPSV;
    }
}

__device__ __forceinline__ float tanh_fast(float x) {
    float y;
    asm("tanh.approx.f32 %0, %1;" : "=f"(y) : "f"(x));
    return y;
}

// One CTA (512 threads) per batch element. tid = j*8 + ci.
//   j  = postsynaptic neuron (0..63), ci = i-chunk (0..7, 8 presynaptic each).
// Octet (8 consecutive lanes, intra-warp) reduces PURE partial sums via 3-level
// bfly shuffles; shared base terms added once after reduction.
// Only 32 param regs/thread -> 2 CTAs/SM -> 32 warps (full occupancy).
__global__ void __launch_bounds__(512, 2) ltc_kernel(
    const float* __restrict__ x,
    const float* __restrict__ ow, const float* __restrict__ ob,
    float* __restrict__ out)
{
    const int b   = blockIdx.x;
    const int tid = threadIdx.x;
    const int j   = tid >> 3;
    const int ci  = tid & 7;

    __shared__ alignas(16) float vbuf[2][UU];

    // Main synapse parameters: this thread's 8 (i, j) pairs, i = ci*8 + k.
    float4 mp[8];
#pragma unroll
    for (int k = 0; k < 8; k++)
        mp[k] = g_P[(ci * 8 + k) * UU + j];

    // Sensory: lanes ci 0..5 each own one input feature i = ci.
    float4 sp = make_float4(0.f, 0.f, 0.f, 0.f);
    if (ci < IIN) sp = g_SP[ci * UU + j];

    const float Cn  = g_Cn[j];
    const float Cd  = g_Cd[j];
    const float cmt = g_cmt[j];

    float owj = 0.f, obj = 0.f;
    if (ci == 0 && j < MSZ) { owj = ow[j]; obj = ob[j]; }

    if (tid < UU) vbuf[0][tid] = 0.f;
    __syncthreads();

    const float* xb   = x   + (size_t)b * TLEN * IIN;
    float*       outb = out + (size_t)b * TLEN * MSZ;

    float xv = (ci < IIN) ? xb[ci] : 0.f;

    int cur = 0;
    for (int t = 0; t < TLEN; t++) {
        // ---- sensory sums (constant across the 6 unfolds) ----
        float sn = 0.f, sd = 0.f;
        if (ci < IIN) {
            float z0 = fmaf(xv, sp.x, sp.y);
            float t0 = tanh_fast(z0);
            sn = sp.z * t0;
            sd = sp.w * t0;
        }
        sn += __shfl_xor_sync(0xffffffffu, sn, 1);
        sd += __shfl_xor_sync(0xffffffffu, sd, 1);
        sn += __shfl_xor_sync(0xffffffffu, sn, 2);
        sd += __shfl_xor_sync(0xffffffffu, sd, 2);
        sn += __shfl_xor_sync(0xffffffffu, sn, 4);
        sd += __shfl_xor_sync(0xffffffffu, sd, 4);
        const float base_n = Cn + sn;   // added exactly once after octet reduction
        const float base_d = Cd + sd;

        // ---- prefetch next timestep's x (hidden under the unfold work) ----
        float nxv = xv;
        {
            int tn = (t + 1 < TLEN) ? (t + 1) : t;
            if (ci < IIN) nxv = xb[tn * IIN + ci];
        }

        // ---- 6 fused semi-implicit Euler unfolds ----
        float vnew = 0.f;
#pragma unroll 1
        for (int u = 0; u < UNFOLDS; u++) {
            const float vj = vbuf[cur][j];
            const float4* vb4 = (const float4*)vbuf[cur];
            const float4 va = vb4[ci * 2 + 0];
            const float4 vB = vb4[ci * 2 + 1];

            // PURE partial sums over this thread's 8 presynaptic i's
            float n0, d0, n1, d1;
            {
                float z, tt;
                z = fmaf(va.x, mp[0].x, mp[0].y); tt = tanh_fast(z);
                n0 = mp[0].z * tt; d0 = mp[0].w * tt;
                z = fmaf(va.y, mp[1].x, mp[1].y); tt = tanh_fast(z);
                n1 = mp[1].z * tt; d1 = mp[1].w * tt;
                z = fmaf(va.z, mp[2].x, mp[2].y); tt = tanh_fast(z);
                n0 = fmaf(mp[2].z, tt, n0); d0 = fmaf(mp[2].w, tt, d0);
                z = fmaf(va.w, mp[3].x, mp[3].y); tt = tanh_fast(z);
                n1 = fmaf(mp[3].z, tt, n1); d1 = fmaf(mp[3].w, tt, d1);
                z = fmaf(vB.x, mp[4].x, mp[4].y); tt = tanh_fast(z);
                n0 = fmaf(mp[4].z, tt, n0); d0 = fmaf(mp[4].w, tt, d0);
                z = fmaf(vB.y, mp[5].x, mp[5].y); tt = tanh_fast(z);
                n1 = fmaf(mp[5].z, tt, n1); d1 = fmaf(mp[5].w, tt, d1);
                z = fmaf(vB.z, mp[6].x, mp[6].y); tt = tanh_fast(z);
                n0 = fmaf(mp[6].z, tt, n0); d0 = fmaf(mp[6].w, tt, d0);
                z = fmaf(vB.w, mp[7].x, mp[7].y); tt = tanh_fast(z);
                n1 = fmaf(mp[7].z, tt, n1); d1 = fmaf(mp[7].w, tt, d1);
            }
            float n = n0 + n1;
            float d = d0 + d1;
            n += __shfl_xor_sync(0xffffffffu, n, 1);
            d += __shfl_xor_sync(0xffffffffu, d, 1);
            n += __shfl_xor_sync(0xffffffffu, n, 2);
            d += __shfl_xor_sync(0xffffffffu, d, 2);
            n += __shfl_xor_sync(0xffffffffu, n, 4);
            d += __shfl_xor_sync(0xffffffffu, d, 4);
            // shared base terms exactly once
            n += fmaf(cmt, vj, base_n);
            d += base_d;
            vnew = __fdividef(n, d);

            if (ci == 0) vbuf[cur ^ 1][j] = vnew;
            __syncthreads();
            cur ^= 1;
        }

        // ---- output: first M motor neurons, affine ----
        if (ci == 0 && j < MSZ)
            outb[t * MSZ + j] = fmaf(vnew, owj, obj);

        xv = nxv;
    }
}

extern "C" void kernel_launch(void* const* d_in, const int* in_sizes, int n_in,
                              void* d_out, int out_size)
{
    // metadata order (setup_inputs dict order):
    // 0 x, 1 gleak, 2 vleak, 3 cm, 4 sigma, 5 mu, 6 w, 7 erev,
    // 8 sensory_sigma, 9 sensory_mu, 10 sensory_w, 11 sensory_erev,
    // 12 input_w, 13 input_b, 14 output_w, 15 output_b
    const float* x     = (const float*)d_in[0];
    const float* gleak = (const float*)d_in[1];
    const float* vleak = (const float*)d_in[2];
    const float* cm    = (const float*)d_in[3];
    const float* sigma = (const float*)d_in[4];
    const float* mu    = (const float*)d_in[5];
    const float* w     = (const float*)d_in[6];
    const float* erev  = (const float*)d_in[7];
    const float* ssig  = (const float*)d_in[8];
    const float* smu   = (const float*)d_in[9];
    const float* sw    = (const float*)d_in[10];
    const float* serev = (const float*)d_in[11];
    const float* iw    = (const float*)d_in[12];
    const float* ib    = (const float*)d_in[13];
    const float* ow    = (const float*)d_in[14];
    const float* ob    = (const float*)d_in[15];

    prep_kernel<<<(UU * UU + 255) / 256, 256>>>(
        gleak, vleak, cm, sigma, mu, w, erev,
        ssig, smu, sw, serev, iw, ib);

    ltc_kernel<<<BSZ, 512>>>(x, ow, ob, (float*)d_out);
}